// round 11
// baseline (speedup 1.0000x reference)
#include <cuda_runtime.h>
#include <cuda_bf16.h>
#include <cstdint>

#define SEQ   512
#define BATCH 256
#define CIN   64
#define HID   128
#define GATES 512   // 4*HID

// -------- scratch (static __device__ arrays; no allocation) --------
__device__ __nv_bfloat16 g_xTb[(size_t)SEQ * BATCH * (2 * CIN)];   // x split pair (S,B,[x1|x2])
__device__ float         g_xg [(size_t)SEQ * BATCH * GATES];       // pre-activations fp32
__device__ __nv_bfloat16 g_y1b[(size_t)SEQ * BATCH * (2 * HID)];   // y1 split pair
__device__ __nv_bfloat16 g_w0b[512 * 2 * CIN];                     // Wih0 split pair
__device__ __nv_bfloat16 g_w1b[512 * 2 * HID];                     // Wih1 split pair

// -------- helpers --------
__device__ __forceinline__ float fast_ex2(float x) {
    float y; asm("ex2.approx.f32 %0, %1;" : "=f"(y) : "f"(x)); return y;
}
__device__ __forceinline__ float fast_rcp(float x) {
    float y; asm("rcp.approx.f32 %0, %1;" : "=f"(y) : "f"(x)); return y;
}
__device__ __forceinline__ float sigmoid_f(float x) {
    float e = fast_ex2(-1.4426950408889634f * x);
    return fast_rcp(1.0f + e);
}
__device__ __forceinline__ float tanh_f(float x) {
    float ax = fabsf(x);
    float e  = fast_ex2(-2.8853900817779268f * ax);
    float r  = fast_rcp(1.0f + e);
    float t  = fmaf(-2.0f * e, r, 1.0f);
    return (x < 0.0f) ? -t : t;
}
__device__ __forceinline__ uint32_t bf2pack(float lo, float hi) {
    uint32_t r;
    asm("cvt.rn.bf16x2.f32 %0, %1, %2;" : "=r"(r) : "f"(hi), "f"(lo));
    return r;
}
__device__ __forceinline__ uint32_t smem_u32(const void* p) {
    return (uint32_t)__cvta_generic_to_shared(p);
}
__device__ __forceinline__ void cp_async16(uint32_t dst, const void* src) {
    asm volatile("cp.async.ca.shared.global [%0], [%1], 16;" :: "r"(dst), "l"(src));
}
#define CP_COMMIT() asm volatile("cp.async.commit_group;" ::: "memory")
#define CP_WAIT0()  asm volatile("cp.async.wait_group 0;" ::: "memory")
__device__ __forceinline__ uint32_t lds32(uint32_t addr) {
    uint32_t v; asm volatile("ld.shared.b32 %0, [%1];" : "=r"(v) : "r"(addr)); return v;
}

// -------- kernel 0: alignment dummy --------
__global__ void k_nop() {}

// -------- kernel 1: transpose + bf16 two-term split: x(B,S,C) -> xTb(S*B, [x1|x2]) --------
__global__ void k_transpose(const float* __restrict__ x) {
    int t = blockIdx.x * blockDim.x + threadIdx.x;
    int c = t & (CIN - 1);
    int sb = t >> 6;
    int b = sb & (BATCH - 1);
    int s = sb >> 8;
    float v = x[((size_t)b * SEQ + s) * CIN + c];
    __nv_bfloat16 a1 = __float2bfloat16(v);
    __nv_bfloat16 a2 = __float2bfloat16(v - __bfloat162float(a1));
    g_xTb[(size_t)sb * (2 * CIN) + c]       = a1;
    g_xTb[(size_t)sb * (2 * CIN) + CIN + c] = a2;
}

// -------- weight split: W(512,K) fp32 -> (512, [W1|W2]) bf16 --------
template <int K, int SEL>
__global__ void k_wsplit(const float* __restrict__ W) {
    __nv_bfloat16* out = SEL ? g_w1b : g_w0b;
    int idx = blockIdx.x * blockDim.x + threadIdx.x;   // over 512*K
    int n = idx / K, k = idx % K;
    float v = W[idx];
    __nv_bfloat16 a1 = __float2bfloat16(v);
    __nv_bfloat16 a2 = __float2bfloat16(v - __bfloat162float(a1));
    out[(size_t)n * (2 * K) + k]     = a1;
    out[(size_t)n * (2 * K) + K + k] = a2;
}

// -------- kernel 2/4: xg = A @ W^T + b1 + b2 via bf16 mma, 3-term split --------
// CTA: 64(M) x 128(N), 256 thr (8 warps, 2x4), load-once smem (A tile + W slice).
// A-frags: 4x LDS.32 (conflict-free: bank = 4g+tig). B-frags: ldmatrix.x4,
// pitch = K2+8 elements (row stride mod 32 banks = 4 -> 8-row groups tile banks).
// Segments: (A1,W1),(A1,W2),(A2,W1); dropped A2W2 ~2^-18.
template <int KIN, int ASEL>
__global__ __launch_bounds__(256) void k_gemm_bf(const float* __restrict__ b1,
                                                 const float* __restrict__ b2) {
    constexpr int K2 = 2 * KIN;
    constexpr int PITCH = K2 + 8;
    const __nv_bfloat16* __restrict__ Ab = ASEL ? g_y1b : g_xTb;
    const __nv_bfloat16* __restrict__ Wb = ASEL ? g_w1b : g_w0b;
    extern __shared__ __nv_bfloat16 smv[];
    __nv_bfloat16* As = smv;                 // [64][PITCH]
    __nv_bfloat16* Ws = smv + 64 * PITCH;    // [128][PITCH]

    const int tid = threadIdx.x;
    const int w = tid >> 5, l = tid & 31, g = l >> 2, tig = l & 3;
    const int mBase = blockIdx.y * 64;
    const int nBase = blockIdx.x * 128;
    const uint32_t sA = smem_u32(As), sW = smem_u32(Ws);

    // load-once via cp.async (16B chunks)
    constexpr int CHR = K2 / 8;
    for (int i = tid; i < 64 * CHR; i += 256) {
        int r = i / CHR, ch = i % CHR;
        cp_async16(sA + (uint32_t)(r * PITCH + ch * 8) * 2,
                   Ab + (size_t)(mBase + r) * K2 + ch * 8);
    }
    for (int i = tid; i < 128 * CHR; i += 256) {
        int r = i / CHR, ch = i % CHR;
        cp_async16(sW + (uint32_t)(r * PITCH + ch * 8) * 2,
                   Wb + (size_t)(nBase + r) * K2 + ch * 8);
    }
    CP_COMMIT();
    CP_WAIT0();
    __syncthreads();

    const int wm = w & 1, wn = w >> 1;
    float acc[2][4][4];
#pragma unroll
    for (int a = 0; a < 2; a++)
#pragma unroll
        for (int b = 0; b < 4; b++)
#pragma unroll
            for (int c = 0; c < 4; c++) acc[a][b][c] = 0.0f;

    const int lrow = ((l >> 4) << 3) + (l & 7);   // ldmatrix row within 16
    const int lkof = ((l >> 3) & 1) * 8;          // ldmatrix k offset (elems)

#pragma unroll
    for (int seg = 0; seg < 3; seg++) {
        const int kA = (seg == 2) ? KIN : 0;
        const int kW = (seg == 1) ? KIN : 0;
#pragma unroll
        for (int ks = 0; ks < KIN / 16; ks++) {
            const int k0A = kA + ks * 16;
            const int k0W = kW + ks * 16;

            uint32_t af[2][4];
#pragma unroll
            for (int mt = 0; mt < 2; mt++) {
                int r0 = wm * 32 + mt * 16 + g;
                uint32_t c0 = (uint32_t)(k0A + 2 * tig) * 2;
                af[mt][0] = lds32(sA + (uint32_t)(r0 * PITCH) * 2 + c0);
                af[mt][1] = lds32(sA + (uint32_t)((r0 + 8) * PITCH) * 2 + c0);
                af[mt][2] = lds32(sA + (uint32_t)(r0 * PITCH) * 2 + c0 + 16u);
                af[mt][3] = lds32(sA + (uint32_t)((r0 + 8) * PITCH) * 2 + c0 + 16u);
            }

            uint32_t bfr[4][2];
#pragma unroll
            for (int h = 0; h < 2; h++) {
                uint32_t addr = sW +
                    (uint32_t)((wn * 32 + h * 16 + lrow) * PITCH + k0W + lkof) * 2;
                uint32_t r0, r1, r2, r3;
                asm volatile("ldmatrix.sync.aligned.m8n8.x4.shared.b16 {%0,%1,%2,%3}, [%4];"
                             : "=r"(r0), "=r"(r1), "=r"(r2), "=r"(r3) : "r"(addr));
                bfr[2 * h][0] = r0;  bfr[2 * h][1] = r1;
                bfr[2 * h + 1][0] = r2;  bfr[2 * h + 1][1] = r3;
            }

#pragma unroll
            for (int mt = 0; mt < 2; mt++)
#pragma unroll
                for (int nt = 0; nt < 4; nt++)
                    asm volatile(
                        "mma.sync.aligned.m16n8k16.row.col.f32.bf16.bf16.f32 "
                        "{%0,%1,%2,%3}, {%4,%5,%6,%7}, {%8,%9}, {%0,%1,%2,%3};"
                        : "+f"(acc[mt][nt][0]), "+f"(acc[mt][nt][1]),
                          "+f"(acc[mt][nt][2]), "+f"(acc[mt][nt][3])
                        : "r"(af[mt][0]), "r"(af[mt][1]), "r"(af[mt][2]), "r"(af[mt][3]),
                          "r"(bfr[nt][0]), "r"(bfr[nt][1]));
        }
    }

    // epilogue: + bias, write fp32
#pragma unroll
    for (int nt = 0; nt < 4; nt++) {
        int col = nBase + wn * 32 + nt * 8 + 2 * tig;
        float bx = b1[col] + b2[col];
        float by = b1[col + 1] + b2[col + 1];
#pragma unroll
        for (int mt = 0; mt < 2; mt++) {
            int row0 = mBase + wm * 32 + mt * 16 + g;
            float2 v0 = make_float2(acc[mt][nt][0] + bx, acc[mt][nt][1] + by);
            float2 v1 = make_float2(acc[mt][nt][2] + bx, acc[mt][nt][3] + by);
            *reinterpret_cast<float2*>(&g_xg[(size_t)row0 * GATES + col])       = v0;
            *reinterpret_cast<float2*>(&g_xg[(size_t)(row0 + 8) * GATES + col]) = v1;
        }
    }
}

// -------- kernel 3/5: LSTM recurrence via warp mma (proven R9) + chain split --------
#define BT_PITCH 136   // 272 B pitch

__global__ __launch_bounds__(512) void k_recur(const float* __restrict__ Whh,
                                               float* __restrict__ out, int layer) {
    __shared__ __align__(16) __nv_bfloat16 BT[2][8][BT_PITCH];
    __shared__ __align__(16) float sa[16][2][32];

    const int tid = threadIdx.x;
    const int w   = tid >> 5, l = tid & 31;
    const int g   = l >> 2, tig = l & 3;
    const int tb  = tig & 1;
    const int q   = g & 3;
    const int b0  = blockIdx.x * 2;

    uint32_t af[2][8][4];
#pragma unroll
    for (int mt = 0; mt < 2; mt++) {
        int r0 = 32 * w + 16 * mt + g;
        int r1 = r0 + 8;
        const float* w0 = Whh + (size_t)((r0 & 3) * HID + (r0 >> 2)) * HID;
        const float* w1 = Whh + (size_t)((r1 & 3) * HID + (r1 >> 2)) * HID;
#pragma unroll
        for (int kt = 0; kt < 8; kt++) {
            int k0 = kt * 16 + 2 * tig;
            float2 v;
            v = *reinterpret_cast<const float2*>(w0 + k0);     af[mt][kt][0] = bf2pack(v.x, v.y);
            v = *reinterpret_cast<const float2*>(w1 + k0);     af[mt][kt][1] = bf2pack(v.x, v.y);
            v = *reinterpret_cast<const float2*>(w0 + k0 + 8); af[mt][kt][2] = bf2pack(v.x, v.y);
            v = *reinterpret_cast<const float2*>(w1 + k0 + 8); af[mt][kt][3] = bf2pack(v.x, v.y);
        }
    }

    for (int i = tid; i < 2 * 8 * BT_PITCH / 2; i += 512)
        reinterpret_cast<uint32_t*>(BT)[i] = 0u;

    int cols[4];
#pragma unroll
    for (int mt = 0; mt < 2; mt++)
#pragma unroll
        for (int rr = 0; rr < 2; rr++)
            cols[mt * 2 + rr] = q * HID + 8 * w + 4 * mt + (g >> 2) + 2 * rr;
    const float* xbase = g_xg + (size_t)(b0 + tb) * GATES;

    float xc[4], xn[4];
#pragma unroll
    for (int i = 0; i < 4; i++) xc[i] = __ldg(xbase + cols[i]);

    const uint32_t btg = (uint32_t)__cvta_generic_to_shared(&BT[0][0][0]);
    const uint32_t lmbase = btg + (uint32_t)(l & 7) * (BT_PITCH * 2) + (uint32_t)(l >> 3) * 16u;

    const int tul = l >> 1, ttb = l & 1, tgu = 8 * w + (l >> 1);

    const float s_in  = (q == 2) ? 2.0f : 1.0f;
    const float s_mul = (q == 2) ? 2.0f : 1.0f;
    const float s_add = (q == 2) ? -1.0f : 0.0f;

    float cstate = 0.0f;
    __syncthreads();

    int p = 0;
    for (int t = 0; t < SEQ; t++) {
        if (t + 1 < SEQ) {
            const float* nb = xbase + (size_t)(t + 1) * BATCH * GATES;
#pragma unroll
            for (int i = 0; i < 4; i++) xn[i] = __ldg(nb + cols[i]);
        }

        uint32_t bfr[4][4];
        const uint32_t lmp = lmbase + (uint32_t)p * (8 * BT_PITCH * 2);
#pragma unroll
        for (int c = 0; c < 4; c++)
            asm volatile("ldmatrix.sync.aligned.m8n8.x4.shared.b16 {%0,%1,%2,%3}, [%4];"
                         : "=r"(bfr[c][0]), "=r"(bfr[c][1]), "=r"(bfr[c][2]), "=r"(bfr[c][3])
                         : "r"(lmp + (uint32_t)c * 64u));

        // two independent 4-deep chains per m-tile (halves exposed HMMA latency)
        float d0a[4] = {0.f, 0.f, 0.f, 0.f}, d0b[4] = {0.f, 0.f, 0.f, 0.f};
        float d1a[4] = {0.f, 0.f, 0.f, 0.f}, d1b[4] = {0.f, 0.f, 0.f, 0.f};
#pragma unroll
        for (int s = 0; s < 8; s++) {
            uint32_t bb0 = bfr[s >> 1][(s & 1) * 2];
            uint32_t bb1 = bfr[s >> 1][(s & 1) * 2 + 1];
            float* t0 = (s < 4) ? d0a : d0b;
            float* t1 = (s < 4) ? d1a : d1b;
            asm volatile(
                "mma.sync.aligned.m16n8k16.row.col.f32.bf16.bf16.f32 "
                "{%0,%1,%2,%3}, {%4,%5,%6,%7}, {%8,%9}, {%0,%1,%2,%3};"
                : "+f"(t0[0]), "+f"(t0[1]), "+f"(t0[2]), "+f"(t0[3])
                : "r"(af[0][s][0]), "r"(af[0][s][1]), "r"(af[0][s][2]), "r"(af[0][s][3]),
                  "r"(bb0), "r"(bb1));
            asm volatile(
                "mma.sync.aligned.m16n8k16.row.col.f32.bf16.bf16.f32 "
                "{%0,%1,%2,%3}, {%4,%5,%6,%7}, {%8,%9}, {%0,%1,%2,%3};"
                : "+f"(t1[0]), "+f"(t1[1]), "+f"(t1[2]), "+f"(t1[3])
                : "r"(af[1][s][0]), "r"(af[1][s][1]), "r"(af[1][s][2]), "r"(af[1][s][3]),
                  "r"(bb0), "r"(bb1));
        }
        float d0[4], d1[4];
#pragma unroll
        for (int i = 0; i < 4; i++) { d0[i] = d0a[i] + d0b[i]; d1[i] = d1a[i] + d1b[i]; }

        float a0m0, a1m0, a0m1, a1m1;
        {
            float s0 = d0[0] + __shfl_xor_sync(0xffffffffu, d0[0], 1);
            float s1 = d0[1] + __shfl_xor_sync(0xffffffffu, d0[1], 1);
            float s2 = d0[2] + __shfl_xor_sync(0xffffffffu, d0[2], 1);
            float s3 = d0[3] + __shfl_xor_sync(0xffffffffu, d0[3], 1);
            float pA = (tb ? s1 : s0) + xc[0];
            float pB = (tb ? s3 : s2) + xc[1];
            a0m0 = fmaf(s_mul, sigmoid_f(s_in * pA), s_add);
            a1m0 = fmaf(s_mul, sigmoid_f(s_in * pB), s_add);
        }
        {
            float s0 = d1[0] + __shfl_xor_sync(0xffffffffu, d1[0], 1);
            float s1 = d1[1] + __shfl_xor_sync(0xffffffffu, d1[1], 1);
            float s2 = d1[2] + __shfl_xor_sync(0xffffffffu, d1[2], 1);
            float s3 = d1[3] + __shfl_xor_sync(0xffffffffu, d1[3], 1);
            float pA = (tb ? s1 : s0) + xc[2];
            float pB = (tb ? s3 : s2) + xc[3];
            a0m1 = fmaf(s_mul, sigmoid_f(s_in * pA), s_add);
            a1m1 = fmaf(s_mul, sigmoid_f(s_in * pB), s_add);
        }

        if (tig < 2) {
            sa[w][tb][g]      = a0m0;
            sa[w][tb][g + 8]  = a1m0;
            sa[w][tb][g + 16] = a0m1;
            sa[w][tb][g + 24] = a1m1;
        }
        __syncwarp();

        if (l < 16) {
            float4 gv = *reinterpret_cast<const float4*>(&sa[w][ttb][tul * 4]);
            cstate = fmaf(gv.y, cstate, gv.x * gv.z);
            float h = gv.w * tanh_f(cstate);
            __nv_bfloat16 h1 = __float2bfloat16(h);
            __nv_bfloat16 h2 = __float2bfloat16(h - __bfloat162float(h1));
            BT[p ^ 1][ttb][tgu]     = h1;
            BT[p ^ 1][ttb + 2][tgu] = h2;
            if (layer == 0) {
                size_t rb = ((size_t)t * BATCH + b0 + ttb) * (size_t)(2 * HID);
                g_y1b[rb + tgu]       = h1;   // split pair feeds gemm1 (error ~2^-17)
                g_y1b[rb + HID + tgu] = h2;
            } else if (t == SEQ - 1) {
                out[(size_t)(b0 + ttb) * HID + tgu] = h;
            }
        }

#pragma unroll
        for (int i = 0; i < 4; i++) xc[i] = xn[i];
        __syncthreads();
        p ^= 1;
    }
}

// -------- launch --------
extern "C" void kernel_launch(void* const* d_in, const int* in_sizes, int n_in,
                              void* d_out, int out_size) {
    const float* x    = (const float*)d_in[0];
    const float* Wih0 = (const float*)d_in[1];
    const float* Whh0 = (const float*)d_in[2];
    const float* bih0 = (const float*)d_in[3];
    const float* bhh0 = (const float*)d_in[4];
    const float* Wih1 = (const float*)d_in[5];
    const float* Whh1 = (const float*)d_in[6];
    const float* bih1 = (const float*)d_in[7];
    const float* bhh1 = (const float*)d_in[8];
    float* out = (float*)d_out;

    constexpr int SMEM0 = (64 + 128) * (2 * CIN + 8) * 2;   // 52224 B
    constexpr int SMEM1 = (64 + 128) * (2 * HID + 8) * 2;   // 101376 B
    cudaFuncSetAttribute(k_gemm_bf<CIN, 0>, cudaFuncAttributeMaxDynamicSharedMemorySize, SMEM0);
    cudaFuncSetAttribute(k_gemm_bf<HID, 1>, cudaFuncAttributeMaxDynamicSharedMemorySize, SMEM1);

    // 0. alignment dummy for ncu slot
    k_nop<<<1, 1>>>();
    // 1. transpose + split x
    k_transpose<<<(SEQ * BATCH * CIN) / 256, 256>>>(x);
    // 1b. weight splits
    k_wsplit<CIN, 0><<<(512 * CIN) / 256, 256>>>(Wih0);
    k_wsplit<HID, 1><<<(512 * HID) / 256, 256>>>(Wih1);
    // 2. xg = x @ Wih0^T + biases (bf16 mma, 3-term)
    k_gemm_bf<CIN, 0><<<dim3(4, (SEQ * BATCH) / 64), 256, SMEM0>>>(bih0, bhh0);
    // 3. layer-0 recurrence (writes y1 split pair)
    k_recur<<<BATCH / 2, 512>>>(Whh0, nullptr, 0);
    // 4. xg = y1 @ Wih1^T + biases
    k_gemm_bf<HID, 1><<<dim3(4, (SEQ * BATCH) / 64), 256, SMEM1>>>(bih1, bhh1);
    // 5. layer-1 recurrence -> out
    k_recur<<<BATCH / 2, 512>>>(Whh1, out, 1);
}

// round 13
// speedup vs baseline: 1.0009x; 1.0009x over previous
#include <cuda_runtime.h>
#include <cuda_bf16.h>
#include <cuda_fp16.h>
#include <cstdint>

#define SEQ 512
#define BATCH 256
#define CIN 64
#define HID 128
#define GATES 512
#define BPI 136   // 16-bit-elem row pitch (272 B)

__device__ __nv_bfloat16 g_xTb[(size_t)SEQ*BATCH*(2*CIN)];
__device__ float         g_xg [(size_t)SEQ*BATCH*GATES];
__device__ __half        g_y1h[(size_t)SEQ*BATCH*(2*HID)];
__device__ __nv_bfloat16 g_w0b[512*2*CIN];
__device__ __half        g_w1p[512*BPI];
__device__ int           g_flag[64];

__device__ __forceinline__ float fast_ex2(float x){float y;asm("ex2.approx.f32 %0,%1;":"=f"(y):"f"(x));return y;}
__device__ __forceinline__ float fast_rcp(float x){float y;asm("rcp.approx.f32 %0,%1;":"=f"(y):"f"(x));return y;}
__device__ __forceinline__ float sigmoid_f(float x){return fast_rcp(1.0f+fast_ex2(-1.4426950408889634f*x));}
__device__ __forceinline__ float tanh_f(float x){
    float ax=fabsf(x),e=fast_ex2(-2.8853900817779268f*ax),r=fast_rcp(1.0f+e);
    float t=fmaf(-2.0f*e,r,1.0f);return (x<0.0f)?-t:t;}
__device__ __forceinline__ uint32_t bf2pack(float lo,float hi){uint32_t r;asm("cvt.rn.bf16x2.f32 %0,%1,%2;":"=r"(r):"f"(hi),"f"(lo));return r;}
__device__ __forceinline__ uint32_t h2pack(float lo,float hi){
    __half2 h=__floats2half2_rn(lo,hi);return *reinterpret_cast<uint32_t*>(&h);}
__device__ __forceinline__ uint32_t smem_u32(const void*p){return (uint32_t)__cvta_generic_to_shared(p);}
__device__ __forceinline__ void cp_async16(uint32_t d,const void*s){asm volatile("cp.async.ca.shared.global [%0],[%1],16;"::"r"(d),"l"(s));}
#define CP_COMMIT() asm volatile("cp.async.commit_group;":::"memory")
#define CP_WAIT0()  asm volatile("cp.async.wait_group 0;":::"memory")
__device__ __forceinline__ uint32_t lds32(uint32_t a){uint32_t v;asm volatile("ld.shared.b32 %0,[%1];":"=r"(v):"r"(a));return v;}
#define LDSM4(r,addr) asm volatile("ldmatrix.sync.aligned.m8n8.x4.shared.b16 {%0,%1,%2,%3},[%4];":"=r"((r)[0]),"=r"((r)[1]),"=r"((r)[2]),"=r"((r)[3]):"r"(addr))
#define MMABF(d,a,b0,b1) asm volatile("mma.sync.aligned.m16n8k16.row.col.f32.bf16.bf16.f32 {%0,%1,%2,%3},{%4,%5,%6,%7},{%8,%9},{%0,%1,%2,%3};":"+f"((d)[0]),"+f"((d)[1]),"+f"((d)[2]),"+f"((d)[3]):"r"((a)[0]),"r"((a)[1]),"r"((a)[2]),"r"((a)[3]),"r"(b0),"r"(b1))
#define MMAF16(d,a,b0,b1) asm volatile("mma.sync.aligned.m16n8k16.row.col.f32.f16.f16.f32 {%0,%1,%2,%3},{%4,%5,%6,%7},{%8,%9},{%0,%1,%2,%3};":"+f"((d)[0]),"+f"((d)[1]),"+f"((d)[2]),"+f"((d)[3]):"r"((a)[0]),"r"((a)[1]),"r"((a)[2]),"r"((a)[3]),"r"(b0),"r"(b1))

__global__ void k_nop() {}

__global__ void k_transpose(const float* __restrict__ x){
    int t=blockIdx.x*blockDim.x+threadIdx.x;
    if(t<64) g_flag[t]=0;
    int c=t&(CIN-1),sb=t>>6,b=sb&(BATCH-1),s=sb>>8;
    float v=x[((size_t)b*SEQ+s)*CIN+c];
    __nv_bfloat16 a1=__float2bfloat16(v);
    __nv_bfloat16 a2=__float2bfloat16(v-__bfloat162float(a1));
    g_xTb[(size_t)sb*(2*CIN)+c]=a1;
    g_xTb[(size_t)sb*(2*CIN)+CIN+c]=a2;
}

__global__ void k_wsplit0(const float* __restrict__ W){
    int idx=blockIdx.x*blockDim.x+threadIdx.x;
    int n=idx/CIN,k=idx%CIN;float v=W[idx];
    __nv_bfloat16 a1=__float2bfloat16(v);
    __nv_bfloat16 a2=__float2bfloat16(v-__bfloat162float(a1));
    g_w0b[(size_t)n*(2*CIN)+k]=a1;
    g_w0b[(size_t)n*(2*CIN)+CIN+k]=a2;
}

__global__ void k_wprep1(const float* __restrict__ W){
    int idx=blockIdx.x*blockDim.x+threadIdx.x;  // 512*128
    int r=idx>>7,k=idx&127;
    g_w1p[(size_t)r*BPI+k]=__float2half(W[((size_t)((r&3)*HID+(r>>2)))*HID+k]);
}

// gemm0: xg0 = x @ Wih0^T + biases (proven R10 path, K=64, bf16 3-term)
__global__ __launch_bounds__(256) void k_gemm_bf0(const float* __restrict__ b1,
                                                  const float* __restrict__ b2){
    constexpr int KIN=CIN,K2=2*KIN,PITCH=K2+8;
    extern __shared__ __nv_bfloat16 smv[];
    __nv_bfloat16* As=smv; __nv_bfloat16* Ws=smv+64*PITCH;
    const int tid=threadIdx.x,w=tid>>5,l=tid&31,g=l>>2,tig=l&3;
    const int mBase=blockIdx.y*64,nBase=blockIdx.x*128;
    const uint32_t sA=smem_u32(As),sW=smem_u32(Ws);
    constexpr int CHR=K2/8;
    for(int i=tid;i<64*CHR;i+=256){int r=i/CHR,ch=i%CHR;
        cp_async16(sA+(uint32_t)(r*PITCH+ch*8)*2,g_xTb+(size_t)(mBase+r)*K2+ch*8);}
    for(int i=tid;i<128*CHR;i+=256){int r=i/CHR,ch=i%CHR;
        cp_async16(sW+(uint32_t)(r*PITCH+ch*8)*2,g_w0b+(size_t)(nBase+r)*K2+ch*8);}
    CP_COMMIT();CP_WAIT0();__syncthreads();
    const int wm=w&1,wn=w>>1;
    float acc[2][4][4];
#pragma unroll
    for(int a=0;a<2;a++)for(int b=0;b<4;b++)for(int c=0;c<4;c++)acc[a][b][c]=0.f;
    const int lrow=((l>>4)<<3)+(l&7),lkof=((l>>3)&1)*8;
#pragma unroll
    for(int seg=0;seg<3;seg++){
        const int kA=(seg==2)?KIN:0,kW=(seg==1)?KIN:0;
#pragma unroll
        for(int ks=0;ks<KIN/16;ks++){
            const int k0A=kA+ks*16,k0W=kW+ks*16;
            uint32_t af[2][4];
#pragma unroll
            for(int mt=0;mt<2;mt++){
                int r0=wm*32+mt*16+g;uint32_t c0=(uint32_t)(k0A+2*tig)*2;
                af[mt][0]=lds32(sA+(uint32_t)(r0*PITCH)*2+c0);
                af[mt][1]=lds32(sA+(uint32_t)((r0+8)*PITCH)*2+c0);
                af[mt][2]=lds32(sA+(uint32_t)(r0*PITCH)*2+c0+16u);
                af[mt][3]=lds32(sA+(uint32_t)((r0+8)*PITCH)*2+c0+16u);}
            uint32_t bfr[4][2];
#pragma unroll
            for(int h=0;h<2;h++){
                uint32_t r4[4];
                LDSM4(r4,sW+(uint32_t)((wn*32+h*16+lrow)*PITCH+k0W+lkof)*2);
                bfr[2*h][0]=r4[0];bfr[2*h][1]=r4[1];bfr[2*h+1][0]=r4[2];bfr[2*h+1][1]=r4[3];}
#pragma unroll
            for(int mt=0;mt<2;mt++)
#pragma unroll
                for(int nt=0;nt<4;nt++) MMABF(acc[mt][nt],af[mt],bfr[nt][0],bfr[nt][1]);
        }
    }
#pragma unroll
    for(int nt=0;nt<4;nt++){
        int col=nBase+wn*32+nt*8+2*tig;
        float bx=b1[col]+b2[col],by=b1[col+1]+b2[col+1];
#pragma unroll
        for(int mt=0;mt<2;mt++){
            int row0=mBase+wm*32+mt*16+g;
            float2 v0=make_float2(acc[mt][nt][0]+bx,acc[mt][nt][1]+by);
            float2 v1=make_float2(acc[mt][nt][2]+bx,acc[mt][nt][3]+by);
            *reinterpret_cast<float2*>(&g_xg[(size_t)row0*GATES+col])=v0;
            *reinterpret_cast<float2*>(&g_xg[(size_t)(row0+8)*GATES+col])=v1;}
    }
}

// fused dual (fp16 recurrent datapath): bid<64 producer (layer 0), else consumer (layer 1)
#define SM_BT  139264
#define SM_BY  (SM_BT+4352)
#define SM_SA  (SM_BY+2176)
#define SM_TOT (SM_SA+8192)

__global__ __launch_bounds__(512,1) void k_dual(const float* __restrict__ Whh0,
                                                const float* __restrict__ Whh1,
                                                const float* __restrict__ bih1,
                                                const float* __restrict__ bhh1,
                                                float* __restrict__ out){
    extern __shared__ char sm[];
    __half* W1P=(__half*)sm;
    __half* BT=(__half*)(sm+SM_BT);   // [2][8][BPI] h splits (fp16)
    __half* BY=(__half*)(sm+SM_BY);   // [8][BPI] y1 splits (fp16)
    float* SA=(float*)(sm+SM_SA);     // [16][4][32]

    const int tid=threadIdx.x,w=tid>>5,l=tid&31,g=l>>2,tig=l&3,q=g&3;
    const bool prod=(blockIdx.x<64);
    const int blk=prod?blockIdx.x:(blockIdx.x-64);
    const int b0=blk*4;
    const float* Whh=prod?Whh0:Whh1;

    // recurrent weight fragments, fp16 (same layout as proven bf16 R9 init)
    uint32_t af[2][8][4];
#pragma unroll
    for(int mt=0;mt<2;mt++){
        int r0=32*w+16*mt+g,r1=r0+8;
        const float* w0=Whh+(size_t)((r0&3)*HID+(r0>>2))*HID;
        const float* w1=Whh+(size_t)((r1&3)*HID+(r1>>2))*HID;
#pragma unroll
        for(int kt=0;kt<8;kt++){
            int k0=kt*16+2*tig;float2 v;
            v=*reinterpret_cast<const float2*>(w0+k0);  af[mt][kt][0]=h2pack(v.x,v.y);
            v=*reinterpret_cast<const float2*>(w1+k0);  af[mt][kt][1]=h2pack(v.x,v.y);
            v=*reinterpret_cast<const float2*>(w0+k0+8);af[mt][kt][2]=h2pack(v.x,v.y);
            v=*reinterpret_cast<const float2*>(w1+k0+8);af[mt][kt][3]=h2pack(v.x,v.y);}
    }

    if(!prod){
        uint32_t dst=smem_u32(W1P);
        for(int i=tid;i<512*BPI/8;i+=512) cp_async16(dst+(uint32_t)i*16,g_w1p+(size_t)i*8);
        CP_COMMIT();
    }
    for(int i=tid;i<2*8*BPI/2;i+=512) reinterpret_cast<uint32_t*>(BT)[i]=0u;

    float bias[4];
    if(!prod){
#pragma unroll
        for(int mt=0;mt<2;mt++)for(int rr=0;rr<2;rr++){
            int col=q*HID+8*w+4*mt+2*rr+(g>>2);
            bias[mt*2+rr]=bih1[col]+bhh1[col];}
    }

    float xc[8],xn[8];
    if(prod&&tig<2){
#pragma unroll
        for(int mt=0;mt<2;mt++)for(int j=0;j<4;j++){
            int col=q*HID+8*w+4*mt+2*(j>>1)+(g>>2);
            xc[mt*4+j]=__ldg(g_xg+((size_t)(b0+2*tig+(j&1)))*GATES+col);}
    }

    if(!prod){CP_WAIT0();}
    __syncthreads();

    const uint32_t btg=smem_u32(BT),byg=smem_u32(BY);
    const uint32_t lmB=(uint32_t)(l&7)*(BPI*2)+(uint32_t)(l>>3)*16u;
    const uint32_t lmA=smem_u32(W1P)+(uint32_t)((32*w+(l&15))*BPI)*2+(uint32_t)(l>>4)*16u;
    const float s_in=(q==2)?2.f:1.f,s_mul=(q==2)?2.f:1.f,s_add=(q==2)?-1.f:0.f;
    const int tb=l&3,tul=l>>2,tgu=8*w+tul;
    float cst=0.f;

    int p=0;
    for(int t=0;t<SEQ;t++){
        float d0a[4]={0,0,0,0},d0b[4]={0,0,0,0},d1a[4]={0,0,0,0},d1b[4]={0,0,0,0};

        if(prod){
            if(tig<2){
                size_t tt=(t+1<SEQ)?(size_t)(t+1):(size_t)t;
#pragma unroll
                for(int mt=0;mt<2;mt++)for(int j=0;j<4;j++){
                    int col=q*HID+8*w+4*mt+2*(j>>1)+(g>>2);
                    xn[mt*4+j]=__ldg(g_xg+(tt*BATCH+b0+2*tig+(j&1))*GATES+col);}
            }
            uint32_t bfr[4][4];
            const uint32_t lmp=btg+(uint32_t)p*(8*BPI*2)+lmB;
#pragma unroll
            for(int c=0;c<4;c++) LDSM4(bfr[c],lmp+(uint32_t)c*64u);
#pragma unroll
            for(int s=0;s<8;s++){
                uint32_t bb0=bfr[s>>1][(s&1)*2],bb1=bfr[s>>1][(s&1)*2+1];
                float* t0=(s<4)?d0a:d0b; float* t1=(s<4)?d1a:d1b;
                MMAF16(t0,af[0][s],bb0,bb1);
                MMAF16(t1,af[1][s],bb0,bb1);}
        } else {
            int f;
            while(true){
                asm volatile("ld.acquire.gpu.global.s32 %0,[%1];":"=r"(f):"l"(g_flag+blk):"memory");
                if(f>t)break;
                __nanosleep(64);
            }
            {   // stage y1[t] splits into BY
                int b=tid>>7,j=tid&127;
                uint32_t yv=*reinterpret_cast<const uint32_t*>(
                    g_y1h+((size_t)t*BATCH+b0+b)*(size_t)(2*HID)+2*j);
                int row=(j<64)?b:(b+4);
                int el=(j<64)?(2*j):(2*j-128);
                *reinterpret_cast<uint32_t*>(BY+row*BPI+el)=yv;
            }
            __syncthreads();
            // pass 1: Wih1 (smem fp16) @ y1 splits
            uint32_t bfy[4][4];
#pragma unroll
            for(int c=0;c<4;c++) LDSM4(bfy[c],byg+lmB+(uint32_t)c*64u);
#pragma unroll
            for(int s=0;s<8;s++){
                uint32_t bb0=bfy[s>>1][(s&1)*2],bb1=bfy[s>>1][(s&1)*2+1];
                uint32_t a[4];
                LDSM4(a,lmA+(uint32_t)(s*16)*2);
                MMAF16(d0a,a,bb0,bb1);
                LDSM4(a,lmA+(uint32_t)(16*BPI+s*16)*2);
                MMAF16(d1a,a,bb0,bb1);}
            // pass 2: Whh1 (regs fp16) @ h splits
            uint32_t bfh[4][4];
            const uint32_t lmp=btg+(uint32_t)p*(8*BPI*2)+lmB;
#pragma unroll
            for(int c=0;c<4;c++) LDSM4(bfh[c],lmp+(uint32_t)c*64u);
#pragma unroll
            for(int s=0;s<8;s++){
                uint32_t bb0=bfh[s>>1][(s&1)*2],bb1=bfh[s>>1][(s&1)*2+1];
                MMAF16(d0b,af[0][s],bb0,bb1);
                MMAF16(d1b,af[1][s],bb0,bb1);}
        }

        // combine chains + split columns (c with c+4): partner lane l^2
        float s0[4],s1[4];
#pragma unroll
        for(int j=0;j<4;j++){
            s0[j]=d0a[j]+d0b[j]; s0[j]+=__shfl_xor_sync(0xffffffffu,s0[j],2);
            s1[j]=d1a[j]+d1b[j]; s1[j]+=__shfl_xor_sync(0xffffffffu,s1[j],2);}

        if(tig<2){
#pragma unroll
            for(int j=0;j<4;j++){
                float p0=s0[j]+(prod?xc[j]:bias[j>>1]);
                float p1=s1[j]+(prod?xc[4+j]:bias[2+(j>>1)]);
                float a0=fmaf(s_mul,sigmoid_f(s_in*p0),s_add);
                float a1=fmaf(s_mul,sigmoid_f(s_in*p1),s_add);
                int b=2*tig+(j&1),rr=j>>1;
                SA[(w*4+b)*32+8*rr+g]=a0;
                SA[(w*4+b)*32+16+8*rr+g]=a1;
            }
        }
        __syncwarp();

        {   // tail: lane owns (batch tb, unit tgu)
            float4 gv=*reinterpret_cast<const float4*>(&SA[(w*4+tb)*32+4*tul]);
            cst=fmaf(gv.y,cst,gv.x*gv.z);
            float h=gv.w*tanh_f(cst);
            __half h1=__float2half(h);
            __half h2=__float2half(h-__half2float(h1));
            BT[(p^1)*8*BPI+tb*BPI+tgu]=h1;
            BT[(p^1)*8*BPI+(tb+4)*BPI+tgu]=h2;
            if(prod){
                size_t rb=((size_t)t*BATCH+b0+tb)*(size_t)(2*HID);
                g_y1h[rb+tgu]=h1;
                g_y1h[rb+HID+tgu]=h2;
            } else if(t==SEQ-1){
                out[(size_t)(b0+tb)*HID+tgu]=h;
            }
        }

        if(prod){
#pragma unroll
            for(int i=0;i<8;i++) xc[i]=xn[i];
        }
        __syncthreads();
        if(prod&&tid==0)
            asm volatile("st.release.gpu.global.s32 [%0],%1;"::"l"(g_flag+blk),"r"(t+1):"memory");
        p^=1;
    }
}

extern "C" void kernel_launch(void* const* d_in, const int* in_sizes, int n_in,
                              void* d_out, int out_size){
    const float* x   =(const float*)d_in[0];
    const float* Wih0=(const float*)d_in[1];
    const float* Whh0=(const float*)d_in[2];
    const float* bih0=(const float*)d_in[3];
    const float* bhh0=(const float*)d_in[4];
    const float* Wih1=(const float*)d_in[5];
    const float* Whh1=(const float*)d_in[6];
    const float* bih1=(const float*)d_in[7];
    const float* bhh1=(const float*)d_in[8];
    float* out=(float*)d_out;

    constexpr int SMEM0=(64+128)*(2*CIN+8)*2;
    cudaFuncSetAttribute(k_gemm_bf0,cudaFuncAttributeMaxDynamicSharedMemorySize,SMEM0);
    cudaFuncSetAttribute(k_dual,cudaFuncAttributeMaxDynamicSharedMemorySize,SM_TOT);

    k_nop<<<1,1>>>();
    k_transpose<<<(SEQ*BATCH*CIN)/256,256>>>(x);
    k_wsplit0<<<(512*CIN)/256,256>>>(Wih0);
    k_wprep1<<<(512*HID)/256,256>>>(Wih1);
    k_gemm_bf0<<<dim3(4,(SEQ*BATCH)/64),256,SMEM0>>>(bih0,bhh0);
    k_dual<<<128,512,SM_TOT>>>(Whh0,Whh1,bih1,bhh1,out);
}

// round 14
// speedup vs baseline: 1.0796x; 1.0786x over previous
#include <cuda_runtime.h>
#include <cuda_bf16.h>
#include <cuda_fp16.h>
#include <cstdint>

#define SEQ 512
#define BATCH 256
#define CIN 64
#define HID 128
#define GATES 512
#define BPI 136   // 16-bit-elem row pitch (272 B)

__device__ __nv_bfloat16 g_xTb[(size_t)SEQ*BATCH*(2*CIN)];
__device__ float         g_xg [(size_t)SEQ*BATCH*GATES];
__device__ __half        g_y1h[(size_t)SEQ*BATCH*(2*HID)];
__device__ __nv_bfloat16 g_w0b[512*2*CIN];
__device__ __half        g_w1p[512*BPI];
__device__ int           g_flag[64];

__device__ __forceinline__ float fast_ex2(float x){float y;asm("ex2.approx.f32 %0,%1;":"=f"(y):"f"(x));return y;}
__device__ __forceinline__ float fast_rcp(float x){float y;asm("rcp.approx.f32 %0,%1;":"=f"(y):"f"(x));return y;}
__device__ __forceinline__ float sigmoid_f(float x){return fast_rcp(1.0f+fast_ex2(-1.4426950408889634f*x));}
__device__ __forceinline__ float tanh_f(float x){
    float ax=fabsf(x),e=fast_ex2(-2.8853900817779268f*ax),r=fast_rcp(1.0f+e);
    float t=fmaf(-2.0f*e,r,1.0f);return (x<0.0f)?-t:t;}
__device__ __forceinline__ uint32_t h2pack(float lo,float hi){
    __half2 h=__floats2half2_rn(lo,hi);return *reinterpret_cast<uint32_t*>(&h);}
__device__ __forceinline__ uint32_t smem_u32(const void*p){return (uint32_t)__cvta_generic_to_shared(p);}
__device__ __forceinline__ void cp_async16(uint32_t d,const void*s){asm volatile("cp.async.ca.shared.global [%0],[%1],16;"::"r"(d),"l"(s));}
__device__ __forceinline__ void cp_async4(uint32_t d,const void*s){asm volatile("cp.async.ca.shared.global [%0],[%1],4;"::"r"(d),"l"(s));}
#define CP_COMMIT() asm volatile("cp.async.commit_group;":::"memory")
#define CP_WAIT0()  asm volatile("cp.async.wait_group 0;":::"memory")
__device__ __forceinline__ uint32_t lds32(uint32_t a){uint32_t v;asm volatile("ld.shared.b32 %0,[%1];":"=r"(v):"r"(a));return v;}
#define LDSM4(r,addr) asm volatile("ldmatrix.sync.aligned.m8n8.x4.shared.b16 {%0,%1,%2,%3},[%4];":"=r"((r)[0]),"=r"((r)[1]),"=r"((r)[2]),"=r"((r)[3]):"r"(addr))
#define MMABF(d,a,b0,b1) asm volatile("mma.sync.aligned.m16n8k16.row.col.f32.bf16.bf16.f32 {%0,%1,%2,%3},{%4,%5,%6,%7},{%8,%9},{%0,%1,%2,%3};":"+f"((d)[0]),"+f"((d)[1]),"+f"((d)[2]),"+f"((d)[3]):"r"((a)[0]),"r"((a)[1]),"r"((a)[2]),"r"((a)[3]),"r"(b0),"r"(b1))
#define MMAF16(d,a,b0,b1) asm volatile("mma.sync.aligned.m16n8k16.row.col.f32.f16.f16.f32 {%0,%1,%2,%3},{%4,%5,%6,%7},{%8,%9},{%0,%1,%2,%3};":"+f"((d)[0]),"+f"((d)[1]),"+f"((d)[2]),"+f"((d)[3]):"r"((a)[0]),"r"((a)[1]),"r"((a)[2]),"r"((a)[3]),"r"(b0),"r"(b1))

__global__ void k_transpose(const float* __restrict__ x){
    int t=blockIdx.x*blockDim.x+threadIdx.x;
    if(t<64) g_flag[t]=0;
    int c=t&(CIN-1),sb=t>>6,b=sb&(BATCH-1),s=sb>>8;
    float v=x[((size_t)b*SEQ+s)*CIN+c];
    __nv_bfloat16 a1=__float2bfloat16(v);
    __nv_bfloat16 a2=__float2bfloat16(v-__bfloat162float(a1));
    g_xTb[(size_t)sb*(2*CIN)+c]=a1;
    g_xTb[(size_t)sb*(2*CIN)+CIN+c]=a2;
}

// merged weight prep: first 512*CIN elems = Wih0 bf16 split; rest = Wih1 fp16 permute
__global__ void k_wprep(const float* __restrict__ W0, const float* __restrict__ W1){
    int idx=blockIdx.x*blockDim.x+threadIdx.x;
    if(idx < 512*CIN){
        int n=idx/CIN,k=idx%CIN;float v=W0[idx];
        __nv_bfloat16 a1=__float2bfloat16(v);
        __nv_bfloat16 a2=__float2bfloat16(v-__bfloat162float(a1));
        g_w0b[(size_t)n*(2*CIN)+k]=a1;
        g_w0b[(size_t)n*(2*CIN)+CIN+k]=a2;
    } else {
        int j=idx-512*CIN;            // 0 .. 512*128-1
        int r=j>>7,k=j&127;
        g_w1p[(size_t)r*BPI+k]=__float2half(W1[((size_t)((r&3)*HID+(r>>2)))*HID+k]);
    }
}

// gemm0: xg0 = x @ Wih0^T + biases (proven, K=64, bf16 3-term)
__global__ __launch_bounds__(256) void k_gemm_bf0(const float* __restrict__ b1,
                                                  const float* __restrict__ b2){
    constexpr int KIN=CIN,K2=2*KIN,PITCH=K2+8;
    extern __shared__ __nv_bfloat16 smv[];
    __nv_bfloat16* As=smv; __nv_bfloat16* Ws=smv+64*PITCH;
    const int tid=threadIdx.x,w=tid>>5,l=tid&31,g=l>>2,tig=l&3;
    const int mBase=blockIdx.y*64,nBase=blockIdx.x*128;
    const uint32_t sA=smem_u32(As),sW=smem_u32(Ws);
    constexpr int CHR=K2/8;
    for(int i=tid;i<64*CHR;i+=256){int r=i/CHR,ch=i%CHR;
        cp_async16(sA+(uint32_t)(r*PITCH+ch*8)*2,g_xTb+(size_t)(mBase+r)*K2+ch*8);}
    for(int i=tid;i<128*CHR;i+=256){int r=i/CHR,ch=i%CHR;
        cp_async16(sW+(uint32_t)(r*PITCH+ch*8)*2,g_w0b+(size_t)(nBase+r)*K2+ch*8);}
    CP_COMMIT();CP_WAIT0();__syncthreads();
    const int wm=w&1,wn=w>>1;
    float acc[2][4][4];
#pragma unroll
    for(int a=0;a<2;a++)for(int b=0;b<4;b++)for(int c=0;c<4;c++)acc[a][b][c]=0.f;
    const int lrow=((l>>4)<<3)+(l&7),lkof=((l>>3)&1)*8;
#pragma unroll
    for(int seg=0;seg<3;seg++){
        const int kA=(seg==2)?KIN:0,kW=(seg==1)?KIN:0;
#pragma unroll
        for(int ks=0;ks<KIN/16;ks++){
            const int k0A=kA+ks*16,k0W=kW+ks*16;
            uint32_t af[2][4];
#pragma unroll
            for(int mt=0;mt<2;mt++){
                int r0=wm*32+mt*16+g;uint32_t c0=(uint32_t)(k0A+2*tig)*2;
                af[mt][0]=lds32(sA+(uint32_t)(r0*PITCH)*2+c0);
                af[mt][1]=lds32(sA+(uint32_t)((r0+8)*PITCH)*2+c0);
                af[mt][2]=lds32(sA+(uint32_t)(r0*PITCH)*2+c0+16u);
                af[mt][3]=lds32(sA+(uint32_t)((r0+8)*PITCH)*2+c0+16u);}
            uint32_t bfr[4][2];
#pragma unroll
            for(int h=0;h<2;h++){
                uint32_t r4[4];
                LDSM4(r4,sW+(uint32_t)((wn*32+h*16+lrow)*PITCH+k0W+lkof)*2);
                bfr[2*h][0]=r4[0];bfr[2*h][1]=r4[1];bfr[2*h+1][0]=r4[2];bfr[2*h+1][1]=r4[3];}
#pragma unroll
            for(int mt=0;mt<2;mt++)
#pragma unroll
                for(int nt=0;nt<4;nt++) MMABF(acc[mt][nt],af[mt],bfr[nt][0],bfr[nt][1]);
        }
    }
#pragma unroll
    for(int nt=0;nt<4;nt++){
        int col=nBase+wn*32+nt*8+2*tig;
        float bx=b1[col]+b2[col],by=b1[col+1]+b2[col+1];
#pragma unroll
        for(int mt=0;mt<2;mt++){
            int row0=mBase+wm*32+mt*16+g;
            float2 v0=make_float2(acc[mt][nt][0]+bx,acc[mt][nt][1]+by);
            float2 v1=make_float2(acc[mt][nt][2]+bx,acc[mt][nt][3]+by);
            *reinterpret_cast<float2*>(&g_xg[(size_t)row0*GATES+col])=v0;
            *reinterpret_cast<float2*>(&g_xg[(size_t)(row0+8)*GATES+col])=v1;}
    }
}

// fused dual (fp16), consumer BY double-buffered with cp.async prefetch of y1[t+1]
#define SM_BT  139264
#define SM_BY  (SM_BT+4352)
#define SM_SA  (SM_BY+8704)        // BY: 2 bufs x 2176 B (rounded to 4352 x2)
#define SM_TOT (SM_SA+8192)

__global__ __launch_bounds__(512,1) void k_dual(const float* __restrict__ Whh0,
                                                const float* __restrict__ Whh1,
                                                const float* __restrict__ bih1,
                                                const float* __restrict__ bhh1,
                                                float* __restrict__ out){
    extern __shared__ char sm[];
    __half* W1P=(__half*)sm;
    __half* BT=(__half*)(sm+SM_BT);   // [2][8][BPI] h splits
    __half* BY=(__half*)(sm+SM_BY);   // [2][8][BPI] y1 splits (double-buffered)
    float* SA=(float*)(sm+SM_SA);     // [16][4][32]

    const int tid=threadIdx.x,w=tid>>5,l=tid&31,g=l>>2,tig=l&3,q=g&3;
    const bool prod=(blockIdx.x<64);
    const int blk=prod?blockIdx.x:(blockIdx.x-64);
    const int b0=blk*4;
    const float* Whh=prod?Whh0:Whh1;

    uint32_t af[2][8][4];
#pragma unroll
    for(int mt=0;mt<2;mt++){
        int r0=32*w+16*mt+g,r1=r0+8;
        const float* w0=Whh+(size_t)((r0&3)*HID+(r0>>2))*HID;
        const float* w1=Whh+(size_t)((r1&3)*HID+(r1>>2))*HID;
#pragma unroll
        for(int kt=0;kt<8;kt++){
            int k0=kt*16+2*tig;float2 v;
            v=*reinterpret_cast<const float2*>(w0+k0);  af[mt][kt][0]=h2pack(v.x,v.y);
            v=*reinterpret_cast<const float2*>(w1+k0);  af[mt][kt][1]=h2pack(v.x,v.y);
            v=*reinterpret_cast<const float2*>(w0+k0+8);af[mt][kt][2]=h2pack(v.x,v.y);
            v=*reinterpret_cast<const float2*>(w1+k0+8);af[mt][kt][3]=h2pack(v.x,v.y);}
    }

    if(!prod){
        uint32_t dst=smem_u32(W1P);
        for(int i=tid;i<512*BPI/8;i+=512) cp_async16(dst+(uint32_t)i*16,g_w1p+(size_t)i*8);
        CP_COMMIT();
    }
    for(int i=tid;i<2*8*BPI/2;i+=512) reinterpret_cast<uint32_t*>(BT)[i]=0u;

    float bias[4];
    if(!prod){
#pragma unroll
        for(int mt=0;mt<2;mt++)for(int rr=0;rr<2;rr++){
            int col=q*HID+8*w+4*mt+2*rr+(g>>2);
            bias[mt*2+rr]=bih1[col]+bhh1[col];}
    }

    float xc[8],xn[8];
    if(prod&&tig<2){
#pragma unroll
        for(int mt=0;mt<2;mt++)for(int j=0;j<4;j++){
            int col=q*HID+8*w+4*mt+2*(j>>1)+(g>>2);
            xc[mt*4+j]=__ldg(g_xg+((size_t)(b0+2*tig+(j&1)))*GATES+col);}
    }

    // consumer y1-staging constants: thread -> one u32 (2 halves) of y1[t]
    const int syb=tid>>7, syj=tid&127;                 // batch-in-4, u32 index
    const int syrow=(syj<64)?syb:(syb+4);
    const int syel=(syj<64)?(2*syj):(2*syj-128);
    const uint32_t byg=smem_u32(BY);
    const uint32_t sydst=byg+(uint32_t)(syrow*BPI+syel)*2;
    const __half* sysrc=g_y1h+((size_t)(b0+syb))*(size_t)(2*HID)+2*syj;

    if(!prod){
        // prologue: wait for y1[0], stage into BY buf 0
        int f;
        do{ asm volatile("ld.acquire.gpu.global.s32 %0,[%1];":"=r"(f):"l"(g_flag+blk):"memory");
            if(f>0)break; __nanosleep(64); }while(true);
        cp_async4(sydst,sysrc);
        CP_COMMIT();
        CP_WAIT0();
    }
    __syncthreads();

    const uint32_t btg=smem_u32(BT);
    const uint32_t lmB=(uint32_t)(l&7)*(BPI*2)+(uint32_t)(l>>3)*16u;
    const uint32_t lmA=smem_u32(W1P)+(uint32_t)((32*w+(l&15))*BPI)*2+(uint32_t)(l>>4)*16u;
    const float s_in=(q==2)?2.f:1.f,s_mul=(q==2)?2.f:1.f,s_add=(q==2)?-1.f:0.f;
    const int tb=l&3,tul=l>>2,tgu=8*w+tul;
    float cst=0.f;

    int p=0;
    for(int t=0;t<SEQ;t++){
        float d0a[4]={0,0,0,0},d0b[4]={0,0,0,0},d1a[4]={0,0,0,0},d1b[4]={0,0,0,0};

        if(prod){
            if(tig<2){
                size_t tt=(t+1<SEQ)?(size_t)(t+1):(size_t)t;
#pragma unroll
                for(int mt=0;mt<2;mt++)for(int j=0;j<4;j++){
                    int col=q*HID+8*w+4*mt+2*(j>>1)+(g>>2);
                    xn[mt*4+j]=__ldg(g_xg+(tt*BATCH+b0+2*tig+(j&1))*GATES+col);}
            }
            uint32_t bfr[4][4];
            const uint32_t lmp=btg+(uint32_t)p*(8*BPI*2)+lmB;
#pragma unroll
            for(int c=0;c<4;c++) LDSM4(bfr[c],lmp+(uint32_t)c*64u);
#pragma unroll
            for(int s=0;s<8;s++){
                uint32_t bb0=bfr[s>>1][(s&1)*2],bb1=bfr[s>>1][(s&1)*2+1];
                float* t0=(s<4)?d0a:d0b; float* t1=(s<4)?d1a:d1b;
                MMAF16(t0,af[0][s],bb0,bb1);
                MMAF16(t1,af[1][s],bb0,bb1);}
        } else {
            // pass 1: Wih1 (smem) @ y1 splits from BY[t&1] (staged last step)
            const uint32_t byp=byg+(uint32_t)(t&1)*(8*BPI*2);
            uint32_t bfy[4][4];
#pragma unroll
            for(int c=0;c<4;c++) LDSM4(bfy[c],byp+lmB+(uint32_t)c*64u);
#pragma unroll
            for(int s=0;s<8;s++){
                uint32_t bb0=bfy[s>>1][(s&1)*2],bb1=bfy[s>>1][(s&1)*2+1];
                uint32_t a[4];
                LDSM4(a,lmA+(uint32_t)(s*16)*2);
                MMAF16(d0a,a,bb0,bb1);
                LDSM4(a,lmA+(uint32_t)(16*BPI+s*16)*2);
                MMAF16(d1a,a,bb0,bb1);}
            // poll + prefetch y1[t+1] into other BY buffer (overlaps pass-2 + tail)
            if(t+1<SEQ){
                int f;
                do{ asm volatile("ld.acquire.gpu.global.s32 %0,[%1];":"=r"(f):"l"(g_flag+blk):"memory");
                    if(f>t+1)break; __nanosleep(64); }while(true);
                cp_async4(sydst+(uint32_t)((t+1)&1)*(8*BPI*2),
                          sysrc+(size_t)(t+1)*BATCH*(2*HID));
                CP_COMMIT();
            }
            // pass 2: Whh1 (regs) @ h splits
            uint32_t bfh[4][4];
            const uint32_t lmp=btg+(uint32_t)p*(8*BPI*2)+lmB;
#pragma unroll
            for(int c=0;c<4;c++) LDSM4(bfh[c],lmp+(uint32_t)c*64u);
#pragma unroll
            for(int s=0;s<8;s++){
                uint32_t bb0=bfh[s>>1][(s&1)*2],bb1=bfh[s>>1][(s&1)*2+1];
                MMAF16(d0b,af[0][s],bb0,bb1);
                MMAF16(d1b,af[1][s],bb0,bb1);}
        }

        float s0[4],s1[4];
#pragma unroll
        for(int j=0;j<4;j++){
            s0[j]=d0a[j]+d0b[j]; s0[j]+=__shfl_xor_sync(0xffffffffu,s0[j],2);
            s1[j]=d1a[j]+d1b[j]; s1[j]+=__shfl_xor_sync(0xffffffffu,s1[j],2);}

        if(tig<2){
#pragma unroll
            for(int j=0;j<4;j++){
                float p0=s0[j]+(prod?xc[j]:bias[j>>1]);
                float p1=s1[j]+(prod?xc[4+j]:bias[2+(j>>1)]);
                float a0=fmaf(s_mul,sigmoid_f(s_in*p0),s_add);
                float a1=fmaf(s_mul,sigmoid_f(s_in*p1),s_add);
                int b=2*tig+(j&1),rr=j>>1;
                SA[(w*4+b)*32+8*rr+g]=a0;
                SA[(w*4+b)*32+16+8*rr+g]=a1;
            }
        }
        __syncwarp();

        {
            float4 gv=*reinterpret_cast<const float4*>(&SA[(w*4+tb)*32+4*tul]);
            cst=fmaf(gv.y,cst,gv.x*gv.z);
            float h=gv.w*tanh_f(cst);
            __half h1=__float2half(h);
            __half h2=__float2half(h-__half2float(h1));
            BT[(p^1)*8*BPI+tb*BPI+tgu]=h1;
            BT[(p^1)*8*BPI+(tb+4)*BPI+tgu]=h2;
            if(prod){
                size_t rb=((size_t)t*BATCH+b0+tb)*(size_t)(2*HID);
                g_y1h[rb+tgu]=h1;
                g_y1h[rb+HID+tgu]=h2;
            } else if(t==SEQ-1){
                out[(size_t)(b0+tb)*HID+tgu]=h;
            }
        }

        if(prod){
#pragma unroll
            for(int i=0;i<8;i++) xc[i]=xn[i];
        } else {
            CP_WAIT0();
        }
        __syncthreads();
        if(prod&&tid==0)
            asm volatile("st.release.gpu.global.s32 [%0],%1;"::"l"(g_flag+blk),"r"(t+1):"memory");
        p^=1;
    }
}

extern "C" void kernel_launch(void* const* d_in, const int* in_sizes, int n_in,
                              void* d_out, int out_size){
    const float* x   =(const float*)d_in[0];
    const float* Wih0=(const float*)d_in[1];
    const float* Whh0=(const float*)d_in[2];
    const float* bih0=(const float*)d_in[3];
    const float* bhh0=(const float*)d_in[4];
    const float* Wih1=(const float*)d_in[5];
    const float* Whh1=(const float*)d_in[6];
    const float* bih1=(const float*)d_in[7];
    const float* bhh1=(const float*)d_in[8];
    float* out=(float*)d_out;

    constexpr int SMEM0=(64+128)*(2*CIN+8)*2;
    cudaFuncSetAttribute(k_gemm_bf0,cudaFuncAttributeMaxDynamicSharedMemorySize,SMEM0);
    cudaFuncSetAttribute(k_dual,cudaFuncAttributeMaxDynamicSharedMemorySize,SM_TOT);

    // launch idx: 0 transpose, 1 wprep, 2 gemm0, 3 dual  (ncu slot = idx 3 -> k_dual)
    k_transpose<<<(SEQ*BATCH*CIN)/256,256>>>(x);
    k_wprep<<<(512*CIN+512*HID)/256,256>>>(Wih0,Wih1);
    k_gemm_bf0<<<dim3(4,(SEQ*BATCH)/64),256,SMEM0>>>(bih0,bhh0);
    k_dual<<<128,512,SM_TOT>>>(Whh0,Whh1,bih1,bhh1,out);
}